// round 2
// baseline (speedup 1.0000x reference)
#include <cuda_runtime.h>
#include <cstdint>

// CostVolume: out[b,d,h,x] = (1/128) * sum_c L[b,c,h,x]*R[b,c,h,x-d], x>=d else 0
// B=8 C=128 H=128 W=240 V=48
#define B_  8
#define C_  128
#define H_  128
#define W_  240
#define V_  48
#define HW_ (H_*W_)

#define CC      16            // channels per chunk
#define NCH     (C_/CC)       // 8 chunks
#define THREADS 128           // 4 warps; warp w handles disparities [12w,12w+12)
#define IT      12            // disparities per thread
#define XT      8             // x's per thread (lane<30 active, xb=8*lane)
#define RWB     1152          // bytes per sR row: (48 pad + 240)*4
#define PADB    192           // left zero pad bytes (48 floats)

typedef unsigned long long ull;

__device__ __forceinline__ uint32_t sw128(uint32_t c) { return c ^ ((c >> 3) & 0x70); }
__device__ __forceinline__ ull pk(float lo, float hi) {
    ull r; asm("mov.b64 %0,{%1,%2};" : "=l"(r) : "f"(lo), "f"(hi)); return r;
}
__device__ __forceinline__ void fma2(ull& a, ull x, ull y) {
    asm("fma.rn.f32x2 %0,%1,%2,%0;" : "+l"(a) : "l"(x), "l"(y));
}
__device__ __forceinline__ ull mul2(ull x, ull y) {
    ull r; asm("mul.rn.f32x2 %0,%1,%2;" : "=l"(r) : "l"(x), "l"(y)); return r;
}
__device__ __forceinline__ ull ldg64(const float* p) {
    ull r; asm("ld.global.nc.b64 %0,[%1];" : "=l"(r) : "l"(p)); return r;
}
__device__ __forceinline__ void lds4(float& a, float& b, float& c, float& d, uint32_t addr) {
    asm volatile("ld.shared.v4.f32 {%0,%1,%2,%3},[%4];"
                 : "=f"(a), "=f"(b), "=f"(c), "=f"(d) : "r"(addr));
}
__device__ __forceinline__ void stg64(float* p, ull v) {
    asm volatile("st.global.b64 [%0],%1;" :: "l"(p), "l"(v));
}

__global__ void __launch_bounds__(THREADS, 3)
cv_kernel(const float* __restrict__ L, const float* __restrict__ R,
          float* __restrict__ out)
{
    extern __shared__ char smem[];   // [2][CC][RWB] swizzled R rows = 36864 B
    const int tid = threadIdx.x;
    const int lane = tid & 31;
    const int w = tid >> 5;
    const int h = blockIdx.x, b = blockIdx.y;
    const uint32_t sbase = (uint32_t)__cvta_generic_to_shared(smem);

    const float* Lbase = L + ((size_t)b * C_ * H_ + h) * W_;
    const float* Rbase = R + ((size_t)b * C_ * H_ + h) * W_;

    // Zero the left pads (col bytes [0,192) of every row, both buffers).
    // This byte range is closed under sw128, so plain zeroing is correct.
    for (int i = tid; i < 2 * CC * 48; i += THREADS) {
        int row = i / 48, k = i - row * 48;
        *(float*)(smem + row * RWB + k * 4) = 0.0f;
    }

    auto load_r = [&](int ch, int buf) {
        const float* src = Rbase + (size_t)ch * CC * HW_;
        #pragma unroll
        for (int q = 0; q < 8; q++) {
            int f = tid + q * THREADS;
            if (f < 960) {                        // 16 rows x 60 float4
                int r = f / 60, col = f - r * 60;
                uint32_t dst = sbase + (uint32_t)(buf * CC + r) * RWB
                             + sw128(PADB + col * 16);
                asm volatile("cp.async.cg.shared.global [%0],[%1],16;"
                             :: "r"(dst), "l"(src + (size_t)r * HW_ + col * 4));
            }
        }
        asm volatile("cp.async.commit_group;");
    };

    const bool act = (lane < 30);
    const int xb = lane * 8;
    const int i0 = w * IT;

    ull acc[IT][4];
    #pragma unroll
    for (int ii = 0; ii < IT; ii++)
        #pragma unroll
        for (int p = 0; p < 4; p++) acc[ii][p] = 0ull;

    load_r(0, 0);

    #pragma unroll 1
    for (int ch = 0; ch < NCH; ch++) {
        const int buf = ch & 1;
        if (ch + 1 < NCH) {
            load_r(ch + 1, (ch + 1) & 1);
            asm volatile("cp.async.wait_group 1;");
        } else {
            asm volatile("cp.async.wait_group 0;");
        }
        __syncthreads();

        if (act) {
            // e[k] = R[xb - i0 - 12 + k], k=0..19, from swizzled smem rows
            const uint32_t base_col = (uint32_t)(4 * (36 + xb - i0)); // bytes, 16B aligned
            uint32_t rowb = sbase + (uint32_t)buf * CC * RWB;
            uint32_t at0 = rowb + sw128(base_col);
            uint32_t at1 = rowb + sw128(base_col + 16);
            uint32_t at2 = rowb + sw128(base_col + 32);
            uint32_t at3 = rowb + sw128(base_col + 48);
            uint32_t at4 = rowb + sw128(base_col + 64);
            const float* lp = Lbase + (size_t)ch * CC * HW_ + xb;

            #pragma unroll 4
            for (int cc = 0; cc < CC; cc++) {
                ull L0 = ldg64(lp);
                ull L1 = ldg64(lp + 2);
                ull L2 = ldg64(lp + 4);
                ull L3 = ldg64(lp + 6);
                lp += HW_;

                float e[20];
                lds4(e[0],  e[1],  e[2],  e[3],  at0);
                lds4(e[4],  e[5],  e[6],  e[7],  at1);
                lds4(e[8],  e[9],  e[10], e[11], at2);
                lds4(e[12], e[13], e[14], e[15], at3);
                lds4(e[16], e[17], e[18], e[19], at4);
                at0 += RWB; at1 += RWB; at2 += RWB; at3 += RWB; at4 += RWB;

                ull pr[19];     // pr[k] = (e[k], e[k+1]); even k are reg-aligned (free)
                #pragma unroll
                for (int k = 1; k <= 18; k++) pr[k] = pk(e[k], e[k + 1]);

                #pragma unroll
                for (int ii = 0; ii < IT; ii++) {
                    fma2(acc[ii][0], L0, pr[12 - ii]);
                    fma2(acc[ii][1], L1, pr[14 - ii]);
                    fma2(acc[ii][2], L2, pr[16 - ii]);
                    fma2(acc[ii][3], L3, pr[18 - ii]);
                }
            }
        }
        __syncthreads();
    }

    if (act) {
        const ull s2 = pk(1.0f / 128.0f, 1.0f / 128.0f);
        float* op = out + (((size_t)b * V_ + i0) * H_ + h) * W_ + xb;
        #pragma unroll
        for (int ii = 0; ii < IT; ii++) {
            stg64(op + 0, mul2(acc[ii][0], s2));
            stg64(op + 2, mul2(acc[ii][1], s2));
            stg64(op + 4, mul2(acc[ii][2], s2));
            stg64(op + 6, mul2(acc[ii][3], s2));
            op += HW_;   // next disparity plane
        }
    }
}

extern "C" void kernel_launch(void* const* d_in, const int* in_sizes, int n_in,
                              void* d_out, int out_size)
{
    const float* L = (const float*)d_in[0];
    const float* R = (const float*)d_in[1];
    float* out = (float*)d_out;

    const int smem_bytes = 2 * CC * RWB;   // 36864
    cudaFuncSetAttribute(cv_kernel, cudaFuncAttributeMaxDynamicSharedMemorySize,
                         smem_bytes);
    cv_kernel<<<dim3(H_, B_), THREADS, smem_bytes>>>(L, R, out);
}

// round 3
// speedup vs baseline: 1.3528x; 1.3528x over previous
#include <cuda_runtime.h>
#include <cstdint>

// CostVolume: out[b,d,h,x] = (1/128) * sum_c L[b,c,h,x]*R[b,c,h,x-d], x>=d else 0
// B=8 C=128 H=128 W=240 V=48
#define B_  8
#define C_  128
#define H_  128
#define W_  240
#define V_  48
#define HW_ (H_*W_)

#define CC      16            // channels per chunk
#define NCH     (C_/CC)       // 8 chunks
#define THREADS 128           // 4 warps; warp w -> disparities [12w, 12w+12)
#define IT      12
#define RPITCH  1152          // R row bytes: (48 pad + 240)*4, multiple of 128
#define LPITCH  1024          // L row bytes: 240*4 = 960, padded to 1024
#define PADB    192           // 48-float left zero pad (R rows)

typedef unsigned long long ull;

// XOR 128B-block index (3 bits) into 16B-unit selector: conflict-free for
// lane-stride-32B LDS.128 access (each 8-lane phase covers all 32 banks).
__device__ __forceinline__ uint32_t sw(uint32_t c) { return c ^ ((c >> 3) & 0x70); }

__device__ __forceinline__ void fma2(ull& a, ull x, ull y) {
    asm("fma.rn.f32x2 %0,%1,%2,%0;" : "+l"(a) : "l"(x), "l"(y));
}
__device__ __forceinline__ ull mul2(ull x, ull y) {
    ull r; asm("mul.rn.f32x2 %0,%1,%2;" : "=l"(r) : "l"(x), "l"(y)); return r;
}
// odd pair: (hi(a), lo(b))
__device__ __forceinline__ ull mkodd(ull a, ull b) {
    ull r;
    asm("{ .reg .f32 x,y,t;\n\t"
        "  mov.b64 {t,x}, %1;\n\t"
        "  mov.b64 {y,t}, %2;\n\t"
        "  mov.b64 %0, {x,y}; }"
        : "=l"(r) : "l"(a), "l"(b));
    return r;
}
__device__ __forceinline__ void lds2x64(ull& a, ull& b, uint32_t addr) {
    asm volatile("ld.shared.v2.b64 {%0,%1},[%2];" : "=l"(a), "=l"(b) : "r"(addr));
}
__device__ __forceinline__ void stg64(float* p, ull v) {
    asm volatile("st.global.b64 [%0],%1;" :: "l"(p), "l"(v));
}

__global__ void __launch_bounds__(THREADS, 3)
cv_kernel(const float* __restrict__ L, const float* __restrict__ R,
          float* __restrict__ out)
{
    extern __shared__ char smem[];
    // layout: R tiles [2][CC][RPITCH] then L tiles [2][CC][LPITCH]
    const uint32_t sb = (uint32_t)__cvta_generic_to_shared(smem);
    const uint32_t sR = sb;
    const uint32_t sL = sb + 2 * CC * RPITCH;

    const int tid = threadIdx.x;
    const int lane = tid & 31;
    const int w = tid >> 5;
    const int h = blockIdx.x, b = blockIdx.y;

    const float* Lbase = L + ((size_t)b * C_ * H_ + h) * W_;
    const float* Rbase = R + ((size_t)b * C_ * H_ + h) * W_;

    // Zero R left pads ([0,192) of every row, closed under sw()).
    for (int i = tid; i < 2 * CC * 48; i += THREADS) {
        int row = i / 48, k = i - row * 48;
        *(float*)(smem + row * RPITCH + k * 4) = 0.0f;
    }

    auto load_tiles = [&](int ch, int buf) {
        const float* lsrc = Lbase + (size_t)ch * CC * HW_;
        const float* rsrc = Rbase + (size_t)ch * CC * HW_;
        #pragma unroll
        for (int q = 0; q < 15; q++) {           // 1920 float4 tasks
            int f = tid + q * THREADS;
            int r = f / 60, col = f - r * 60;    // r in [0,32)
            if (r < 16) {                        // R rows
                uint32_t d = sR + (uint32_t)(buf * CC + r) * RPITCH
                           + sw(PADB + col * 16);
                asm volatile("cp.async.cg.shared.global [%0],[%1],16;"
                             :: "r"(d), "l"(rsrc + (size_t)r * HW_ + col * 4));
            } else {                             // L rows
                int r2 = r - 16;
                uint32_t d = sL + (uint32_t)(buf * CC + r2) * LPITCH
                           + sw(col * 16);
                asm volatile("cp.async.cg.shared.global [%0],[%1],16;"
                             :: "r"(d), "l"(lsrc + (size_t)r2 * HW_ + col * 4));
            }
        }
        asm volatile("cp.async.commit_group;");
    };

    const bool act = (lane < 30);
    const int xb = lane * 8;     // 8 x's per thread
    const int i0 = w * IT;       // 12 disparities per warp

    ull acc[IT][4];
    #pragma unroll
    for (int ii = 0; ii < IT; ii++)
        #pragma unroll
        for (int t = 0; t < 4; t++) acc[ii][t] = 0ull;

    load_tiles(0, 0);

    #pragma unroll 1
    for (int ch = 0; ch < NCH; ch++) {
        const int buf = ch & 1;
        if (ch + 1 < NCH) {
            load_tiles(ch + 1, (ch + 1) & 1);
            asm volatile("cp.async.wait_group 1;");
        } else {
            asm volatile("cp.async.wait_group 0;");
        }
        __syncthreads();

        if (act) {
            // e[k] = R[xb - i0 - 12 + k], k = 0..19 (base byte is 16B aligned)
            const uint32_t bc = (uint32_t)(4 * (36 + xb - i0));  // incl. 48-pad
            uint32_t ra0 = sR + (uint32_t)buf * CC * RPITCH + sw(bc);
            uint32_t ra1 = sR + (uint32_t)buf * CC * RPITCH + sw(bc + 16);
            uint32_t ra2 = sR + (uint32_t)buf * CC * RPITCH + sw(bc + 32);
            uint32_t ra3 = sR + (uint32_t)buf * CC * RPITCH + sw(bc + 48);
            uint32_t ra4 = sR + (uint32_t)buf * CC * RPITCH + sw(bc + 64);
            uint32_t la0 = sL + (uint32_t)buf * CC * LPITCH + sw((uint32_t)xb * 4);
            uint32_t la1 = sL + (uint32_t)buf * CC * LPITCH + sw((uint32_t)xb * 4 + 16);

            #pragma unroll 2
            for (int cc = 0; cc < CC; cc++) {
                ull Lp[4];                        // (L[xb+2t], L[xb+2t+1])
                lds2x64(Lp[0], Lp[1], la0);
                lds2x64(Lp[2], Lp[3], la1);
                la0 += LPITCH; la1 += LPITCH;

                ull E[10];                        // E[m] = (e[2m], e[2m+1]) = pr[2m]
                lds2x64(E[0], E[1], ra0);
                lds2x64(E[2], E[3], ra1);
                lds2x64(E[4], E[5], ra2);
                lds2x64(E[6], E[7], ra3);
                lds2x64(E[8], E[9], ra4);
                ra0 += RPITCH; ra1 += RPITCH; ra2 += RPITCH;
                ra3 += RPITCH; ra4 += RPITCH;

                ull O[9];                         // O[m] = pr[2m+1]
                #pragma unroll
                for (int m = 0; m < 9; m++) O[m] = mkodd(E[m], E[m + 1]);

                // acc[ii][t] += Lp[t] * pr[2t + 12 - ii]
                #pragma unroll
                for (int ii = 0; ii < IT; ii++) {
                    #pragma unroll
                    for (int t = 0; t < 4; t++) {
                        int k = 2 * t + 12 - ii;
                        if (k & 1) fma2(acc[ii][t], Lp[t], O[k >> 1]);
                        else       fma2(acc[ii][t], Lp[t], E[k >> 1]);
                    }
                }
            }
        }
        __syncthreads();
    }

    if (act) {
        ull s2; { float s = 1.0f / 128.0f;
                  asm("mov.b64 %0,{%1,%1};" : "=l"(s2) : "f"(s)); }
        float* op = out + (((size_t)b * V_ + i0) * H_ + h) * W_ + xb;
        #pragma unroll
        for (int ii = 0; ii < IT; ii++) {
            stg64(op + 0, mul2(acc[ii][0], s2));
            stg64(op + 2, mul2(acc[ii][1], s2));
            stg64(op + 4, mul2(acc[ii][2], s2));
            stg64(op + 6, mul2(acc[ii][3], s2));
            op += HW_;
        }
    }
}

extern "C" void kernel_launch(void* const* d_in, const int* in_sizes, int n_in,
                              void* d_out, int out_size)
{
    const float* L = (const float*)d_in[0];
    const float* R = (const float*)d_in[1];
    float* out = (float*)d_out;

    const int smem_bytes = 2 * CC * RPITCH + 2 * CC * LPITCH;  // 69632
    cudaFuncSetAttribute(cv_kernel, cudaFuncAttributeMaxDynamicSharedMemorySize,
                         smem_bytes);
    cv_kernel<<<dim3(H_, B_), THREADS, smem_bytes>>>(L, R, out);
}

// round 4
// speedup vs baseline: 1.4427x; 1.0664x over previous
#include <cuda_runtime.h>
#include <cstdint>

// CostVolume: out[b,d,h,x] = (1/128) * sum_c L[b,c,h,x]*R[b,c,h,x-d], x>=d else 0
// B=8 C=128 H=128 W=240 V=48
#define B_  8
#define C_  128
#define H_  128
#define W_  240
#define V_  48
#define HW_ (H_*W_)

#define CC      16            // channels per chunk
#define NCH     (C_/CC)       // 8 chunks
#define THREADS 128           // 4 warps; warp w -> disparities [12w, 12w+12)
#define IT      12
#define RPITCH  1152          // R row bytes: (48 pad + 240)*4
#define LPITCH  1024          // L row bytes: 240*4=960 -> 1024
#define PADB    192           // 48-float left zero pad on R rows

typedef unsigned long long ull;

// col-local swizzle (within a row): XOR 128B-block bits into 16B-unit bits.
// Applied identically on store (cp.async) and load, so correctness is layout-
// internal. Makes lane-stride-32B LDS.128 conflict-free.
__device__ __forceinline__ uint32_t sw(uint32_t c) { return c ^ ((c >> 3) & 0x70); }

__device__ __forceinline__ ull pk(float lo, float hi) {
    ull r; asm("mov.b64 %0,{%1,%2};" : "=l"(r) : "f"(lo), "f"(hi)); return r;
}
__device__ __forceinline__ void upk(ull v, float& lo, float& hi) {
    asm("mov.b64 {%0,%1},%2;" : "=f"(lo), "=f"(hi) : "l"(v));
}
__device__ __forceinline__ void fma2(ull& a, ull x, ull y) {
    asm("fma.rn.f32x2 %0,%1,%2,%0;" : "+l"(a) : "l"(x), "l"(y));
}

__global__ void __launch_bounds__(THREADS, 3)
cv_kernel(const float* __restrict__ L, const float* __restrict__ R,
          float* __restrict__ out)
{
    extern __shared__ char smem[];
    // layout: R tiles [2][CC][RPITCH] then L tiles [2][CC][LPITCH]
    char* const smR = smem;
    char* const smL = smem + 2 * CC * RPITCH;
    const uint32_t sRa = (uint32_t)__cvta_generic_to_shared(smR);
    const uint32_t sLa = (uint32_t)__cvta_generic_to_shared(smL);

    const int tid = threadIdx.x;
    const int lane = tid & 31;
    const int w = tid >> 5;
    const int h = blockIdx.x, b = blockIdx.y;

    const float* Lbase = L + ((size_t)b * C_ * H_ + h) * W_;
    const float* Rbase = R + ((size_t)b * C_ * H_ + h) * W_;

    // Zero R left pads (bytes [0,192) of each row; closed under sw()).
    for (int i = tid; i < 2 * CC * 48; i += THREADS) {
        int row = i / 48, k = i - row * 48;
        *(float*)(smR + row * RPITCH + k * 4) = 0.0f;
    }

    auto load_tiles = [&](int ch, int buf) {
        const float* lsrc = Lbase + (size_t)ch * CC * HW_;
        const float* rsrc = Rbase + (size_t)ch * CC * HW_;
        #pragma unroll
        for (int q = 0; q < 15; q++) {           // 1920 float4 tasks
            int f = tid + q * THREADS;
            int r = f / 60, col = f - r * 60;    // r in [0,32)
            if (r < 16) {                        // R rows
                uint32_t d = sRa + (uint32_t)(buf * CC + r) * RPITCH
                           + sw(PADB + col * 16);
                asm volatile("cp.async.cg.shared.global [%0],[%1],16;"
                             :: "r"(d), "l"(rsrc + (size_t)r * HW_ + col * 4));
            } else {                             // L rows
                int r2 = r - 16;
                uint32_t d = sLa + (uint32_t)(buf * CC + r2) * LPITCH
                           + sw(col * 16);
                asm volatile("cp.async.cg.shared.global [%0],[%1],16;"
                             :: "r"(d), "l"(lsrc + (size_t)r2 * HW_ + col * 4));
            }
        }
        asm volatile("cp.async.commit_group;");
    };

    const bool act = (lane < 30);
    const int xb = lane * 8;     // 8 x's per thread
    const int i0 = w * IT;       // 12 disparities per warp

    ull acc[IT][4];
    #pragma unroll
    for (int ii = 0; ii < IT; ii++)
        #pragma unroll
        for (int t = 0; t < 4; t++) acc[ii][t] = 0ull;

    // Swizzled column offsets (within-row), fixed for the whole kernel.
    const uint32_t bc = (uint32_t)(4 * (36 + xb - i0));  // 16B aligned
    const uint32_t rc0 = sw(bc),      rc1 = sw(bc + 16), rc2 = sw(bc + 32);
    const uint32_t rc3 = sw(bc + 48), rc4 = sw(bc + 64);
    const uint32_t lc0 = sw((uint32_t)xb * 4), lc1 = sw((uint32_t)xb * 4 + 16);

    load_tiles(0, 0);

    #pragma unroll 1
    for (int ch = 0; ch < NCH; ch++) {
        const int buf = ch & 1;
        if (ch + 1 < NCH) {
            load_tiles(ch + 1, (ch + 1) & 1);
            asm volatile("cp.async.wait_group 1;");
        } else {
            asm volatile("cp.async.wait_group 0;");
        }
        __syncthreads();

        if (act) {
            // Base pointers once per chunk; cc loop uses constant indices only
            // -> LDS [R+imm], zero inner-loop address arithmetic.
            const char* rb = smR + (size_t)buf * CC * RPITCH;
            const char* lb = smL + (size_t)buf * CC * LPITCH;
            const float4* q0 = (const float4*)(rb + rc0);
            const float4* q1 = (const float4*)(rb + rc1);
            const float4* q2 = (const float4*)(rb + rc2);
            const float4* q3 = (const float4*)(rb + rc3);
            const float4* q4 = (const float4*)(rb + rc4);
            const float4* p0 = (const float4*)(lb + lc0);
            const float4* p1 = (const float4*)(lb + lc1);
            #define RSTEP (RPITCH / 16)
            #define LSTEP (LPITCH / 16)

            #pragma unroll
            for (int cc = 0; cc < CC; cc++) {
                float4 Lq0 = p0[cc * LSTEP];
                float4 Lq1 = p1[cc * LSTEP];
                ull La0 = pk(Lq0.x, Lq0.y);
                ull La1 = pk(Lq0.z, Lq0.w);
                ull La2 = pk(Lq1.x, Lq1.y);
                ull La3 = pk(Lq1.z, Lq1.w);

                float e[20];
                float4 v;
                v = q0[cc * RSTEP]; e[0]=v.x; e[1]=v.y; e[2]=v.z; e[3]=v.w;
                v = q1[cc * RSTEP]; e[4]=v.x; e[5]=v.y; e[6]=v.z; e[7]=v.w;
                v = q2[cc * RSTEP]; e[8]=v.x; e[9]=v.y; e[10]=v.z; e[11]=v.w;
                v = q3[cc * RSTEP]; e[12]=v.x; e[13]=v.y; e[14]=v.z; e[15]=v.w;
                v = q4[cc * RSTEP]; e[16]=v.x; e[17]=v.y; e[18]=v.z; e[19]=v.w;

                ull pr[19];          // pr[k] = (e[k], e[k+1]); even k alias quads
                #pragma unroll
                for (int k = 1; k <= 18; k++) pr[k] = pk(e[k], e[k + 1]);

                #pragma unroll
                for (int ii = 0; ii < IT; ii++) {
                    fma2(acc[ii][0], La0, pr[12 - ii]);
                    fma2(acc[ii][1], La1, pr[14 - ii]);
                    fma2(acc[ii][2], La2, pr[16 - ii]);
                    fma2(acc[ii][3], La3, pr[18 - ii]);
                }
            }
        }
        __syncthreads();
    }

    if (act) {
        const float s = 1.0f / 128.0f;
        float* op = out + (((size_t)b * V_ + i0) * H_ + h) * W_ + xb;
        #pragma unroll
        for (int ii = 0; ii < IT; ii++) {
            float a0,a1,a2,a3,a4,a5,a6,a7;
            upk(acc[ii][0], a0, a1);
            upk(acc[ii][1], a2, a3);
            upk(acc[ii][2], a4, a5);
            upk(acc[ii][3], a6, a7);
            float4 o0, o1;
            o0.x=a0*s; o0.y=a1*s; o0.z=a2*s; o0.w=a3*s;
            o1.x=a4*s; o1.y=a5*s; o1.z=a6*s; o1.w=a7*s;
            *(float4*)(op)     = o0;
            *(float4*)(op + 4) = o1;
            op += HW_;
        }
    }
}

extern "C" void kernel_launch(void* const* d_in, const int* in_sizes, int n_in,
                              void* d_out, int out_size)
{
    const float* L = (const float*)d_in[0];
    const float* R = (const float*)d_in[1];
    float* out = (float*)d_out;

    const int smem_bytes = 2 * CC * RPITCH + 2 * CC * LPITCH;  // 69632
    cudaFuncSetAttribute(cv_kernel, cudaFuncAttributeMaxDynamicSharedMemorySize,
                         smem_bytes);
    cv_kernel<<<dim3(H_, B_), THREADS, smem_bytes>>>(L, R, out);
}

// round 5
// speedup vs baseline: 1.8296x; 1.2682x over previous
#include <cuda_runtime.h>
#include <cstdint>

// CostVolume: out[b,d,h,x] = (1/128) * sum_c L[b,c,h,x]*R[b,c,h,x-d], x>=d else 0
// B=8 C=128 H=128 W=240 V=48
#define B_  8
#define C_  128
#define H_  128
#define W_  240
#define V_  48
#define HW_ (H_*W_)

#define CC   16            // channels per chunk
#define NCH  (C_/CC)       // 8 chunks
#define THREADS 128
#define IT   24            // disparities per thread (2 i-groups)
#define RW   288           // sR row width: 48 zero pad + 240 data

__device__ __forceinline__ unsigned long long pk(float lo, float hi) {
    unsigned long long r;
    asm("mov.b64 %0, {%1, %2};" : "=l"(r) : "f"(lo), "f"(hi));
    return r;
}
__device__ __forceinline__ void upk(unsigned long long v, float& lo, float& hi) {
    asm("mov.b64 {%0, %1}, %2;" : "=f"(lo), "=f"(hi) : "l"(v));
}
__device__ __forceinline__ void fma2(unsigned long long& acc,
                                     unsigned long long a, unsigned long long b) {
    asm("fma.rn.f32x2 %0, %1, %2, %0;" : "+l"(acc) : "l"(a), "l"(b));
}
__device__ __forceinline__ void cpasync16(uint32_t saddr, const void* g) {
    asm volatile("cp.async.cg.shared.global [%0], [%1], 16;" :: "r"(saddr), "l"(g));
}

__global__ void __launch_bounds__(THREADS, 3)
cv_kernel(const float* __restrict__ L, const float* __restrict__ R,
          float* __restrict__ out)
{
    extern __shared__ float smem[];
    float* sL = smem;                 // [2][CC][W_]   = 2*16*240 floats
    float* sR = smem + 2 * CC * W_;   // [2][CC][RW]   = 2*16*288 floats

    const int tid = threadIdx.x;
    const int h = blockIdx.x;
    const int b = blockIdx.y;

    const int xg = tid & 63;          // 0..63 (60 active)
    const int ig = tid >> 6;          // 0..1
    const int i0 = ig * IT;
    const int xb = xg * 4;
    const bool act = (xg < 60);

    const float* Lbase = L + ((size_t)b * C_ * H_ + h) * W_;  // + c*HW_ + x
    const float* Rbase = R + ((size_t)b * C_ * H_ + h) * W_;

    // Zero the left pad of sR (j<0 -> 0), both buffers, once.
    for (int idx = tid; idx < 2 * CC * 48; idx += THREADS) {
        int buf = idx / (CC * 48);
        int rem = idx - buf * (CC * 48);
        int r = rem / 48, k = rem - r * 48;
        sR[buf * (CC * RW) + r * RW + k] = 0.0f;
    }

    unsigned long long acc[IT][2];
    #pragma unroll
    for (int ii = 0; ii < IT; ii++) { acc[ii][0] = 0ull; acc[ii][1] = 0ull; }

    auto issue_load = [&](int ch, int buf) {
        const int c0 = ch * CC;
        #pragma unroll
        for (int q = 0; q < 15; q++) {           // 1920 float4 ops / 128 thr
            int f = tid + q * THREADS;
            if (f < 960) {                        // L tile
                int r = f / 60, col = (f - r * 60) * 4;
                uint32_t d = (uint32_t)__cvta_generic_to_shared(
                    &sL[buf * (CC * W_) + r * W_ + col]);
                cpasync16(d, Lbase + (size_t)(c0 + r) * HW_ + col);
            } else {                              // R tile (offset 48)
                int f2 = f - 960;
                int r = f2 / 60, col = (f2 - r * 60) * 4;
                uint32_t d = (uint32_t)__cvta_generic_to_shared(
                    &sR[buf * (CC * RW) + r * RW + 48 + col]);
                cpasync16(d, Rbase + (size_t)(c0 + r) * HW_ + col);
            }
        }
        asm volatile("cp.async.commit_group;");
    };

    issue_load(0, 0);

    #pragma unroll 1
    for (int ch = 0; ch < NCH; ch++) {
        const int buf = ch & 1;
        if (ch + 1 < NCH) {
            issue_load(ch + 1, (ch + 1) & 1);
            asm volatile("cp.async.wait_group 1;");
        } else {
            asm volatile("cp.async.wait_group 0;");
        }
        __syncthreads();

        if (act) {
            const float* bL = &sL[buf * (CC * W_)];
            const float* bR = &sR[buf * (CC * RW)];
            const int ab = xb - i0 + 24;  // aligned (mod 4) window base in sR row
            #pragma unroll
            for (int cc = 0; cc < CC; cc++) {
                float4 Lq = *(const float4*)(bL + cc * W_ + xb);
                unsigned long long La = pk(Lq.x, Lq.y);
                unsigned long long Lb = pk(Lq.z, Lq.w);

                float r_[28];
                #pragma unroll
                for (int m = 0; m < 7; m++) {
                    float4 qv = *(const float4*)(bR + cc * RW + ab + 4 * m);
                    r_[4*m+0] = qv.x; r_[4*m+1] = qv.y;
                    r_[4*m+2] = qv.z; r_[4*m+3] = qv.w;
                }
                // r_[k] = R[xb - i0 + k - 24]
                unsigned long long pr[27];
                #pragma unroll
                for (int k = 1; k <= 26; k++) pr[k] = pk(r_[k], r_[k + 1]);

                #pragma unroll
                for (int ii = 0; ii < IT; ii++) {
                    // d = i0+ii; x pair (xb,xb+1): R pair at k=24-ii
                    fma2(acc[ii][0], La, pr[24 - ii]);
                    // x pair (xb+2,xb+3): R pair at k=26-ii
                    fma2(acc[ii][1], Lb, pr[26 - ii]);
                }
            }
        }
        __syncthreads();
    }

    if (act) {
        const float s = 1.0f / 128.0f;
        #pragma unroll
        for (int ii = 0; ii < IT; ii++) {
            int d = i0 + ii;
            float a0, a1, a2, a3;
            upk(acc[ii][0], a0, a1);
            upk(acc[ii][1], a2, a3);
            float4 o;
            o.x = a0 * s; o.y = a1 * s; o.z = a2 * s; o.w = a3 * s;
            *(float4*)(out + (((size_t)b * V_ + d) * H_ + h) * W_ + xb) = o;
        }
    }
}

extern "C" void kernel_launch(void* const* d_in, const int* in_sizes, int n_in,
                              void* d_out, int out_size)
{
    const float* L = (const float*)d_in[0];
    const float* R = (const float*)d_in[1];
    float* out = (float*)d_out;

    const int smem_bytes = (2 * CC * W_ + 2 * CC * RW) * (int)sizeof(float); // 67584
    cudaFuncSetAttribute(cv_kernel, cudaFuncAttributeMaxDynamicSharedMemorySize,
                         smem_bytes);
    cv_kernel<<<dim3(H_, B_), THREADS, smem_bytes>>>(L, R, out);
}

// round 7
// speedup vs baseline: 1.9944x; 1.0900x over previous
#include <cuda_runtime.h>
#include <cstdint>

// CostVolume: out[b,d,h,x] = (1/128) * sum_c L[b,c,h,x]*R[b,c,h,x-d], x>=d else 0
// B=8 C=128 H=128 W=240 V=48
// Parity-phased x-pairing: even d pairs (xb+2t,xb+2t+1), odd d pairs
// (xb+2t+1,xb+2t+2) -> all R operand pairs are ALIGNED quad halves (no MOVs).
#define B_  8
#define C_  128
#define H_  128
#define W_  240
#define V_  48
#define HW_ (H_*W_)

#define CC   16            // channels per chunk
#define NCH  (C_/CC)       // 8 chunks
#define THREADS 128
#define RW   288           // sR row width: 48 zero pad + 240 data

typedef unsigned long long ull;

__device__ __forceinline__ ull pk(float lo, float hi) {
    ull r; asm("mov.b64 %0, {%1, %2};" : "=l"(r) : "f"(lo), "f"(hi)); return r;
}
__device__ __forceinline__ void upk(ull v, float& lo, float& hi) {
    asm("mov.b64 {%0, %1}, %2;" : "=f"(lo), "=f"(hi) : "l"(v));
}
__device__ __forceinline__ void fma2(ull& acc, ull a, ull b) {
    asm("fma.rn.f32x2 %0, %1, %2, %0;" : "+l"(acc) : "l"(a), "l"(b));
}
__device__ __forceinline__ void cpasync16(uint32_t saddr, const void* g) {
    asm volatile("cp.async.cg.shared.global [%0], [%1], 16;" :: "r"(saddr), "l"(g));
}

__global__ void __launch_bounds__(THREADS, 3)
cv_kernel(const float* __restrict__ L, const float* __restrict__ R,
          float* __restrict__ out)
{
    extern __shared__ float smem[];
    float* sL = smem;                 // [2][CC][W_]  (L first: +1 overread lands in sR)
    float* sR = smem + 2 * CC * W_;   // [2][CC][RW]

    const int tid = threadIdx.x;
    const int h = blockIdx.x;
    const int b = blockIdx.y;

    const int xg = tid & 63;          // 0..63 (60 active)
    const int ig = tid >> 6;          // 0..1
    const int i0 = ig * 24;           // this group's disparity base
    const int xb = xg * 4;
    const bool act = (xg < 60);

    const float* Lbase = L + ((size_t)b * C_ * H_ + h) * W_;
    const float* Rbase = R + ((size_t)b * C_ * H_ + h) * W_;

    // Zero the left pad of sR (x<0 -> 0), both buffers, once.
    for (int idx = tid; idx < 2 * CC * 48; idx += THREADS) {
        int buf = idx / (CC * 48);
        int rem = idx - buf * (CC * 48);
        int r = rem / 48, k = rem - r * 48;
        sR[buf * (CC * RW) + r * RW + k] = 0.0f;
    }

    // accE[j]: d = i0+2j, x pairs (xb,xb+1),(xb+2,xb+3)
    // accO[j]: d = i0+2j+1, x pairs (xb+1,xb+2),(xb+3,xb+4)
    ull accE[12][2], accO[12][2];
    #pragma unroll
    for (int j = 0; j < 12; j++) {
        accE[j][0] = 0ull; accE[j][1] = 0ull;
        accO[j][0] = 0ull; accO[j][1] = 0ull;
    }

    auto issue_load = [&](int ch, int buf) {
        const int c0 = ch * CC;
        #pragma unroll
        for (int q = 0; q < 15; q++) {           // 1920 float4 ops / 128 thr
            int f = tid + q * THREADS;
            if (f < 960) {                        // L tile
                int r = f / 60, col = (f - r * 60) * 4;
                uint32_t d = (uint32_t)__cvta_generic_to_shared(
                    &sL[buf * (CC * W_) + r * W_ + col]);
                cpasync16(d, Lbase + (size_t)(c0 + r) * HW_ + col);
            } else {                              // R tile (offset 48)
                int f2 = f - 960;
                int r = f2 / 60, col = (f2 - r * 60) * 4;
                uint32_t d = (uint32_t)__cvta_generic_to_shared(
                    &sR[buf * (CC * RW) + r * RW + 48 + col]);
                cpasync16(d, Rbase + (size_t)(c0 + r) * HW_ + col);
            }
        }
        asm volatile("cp.async.commit_group;");
    };

    issue_load(0, 0);

    #pragma unroll 1
    for (int ch = 0; ch < NCH; ch++) {
        const int buf = ch & 1;
        if (ch + 1 < NCH) {
            issue_load(ch + 1, (ch + 1) & 1);
            asm volatile("cp.async.wait_group 1;");
        } else {
            asm volatile("cp.async.wait_group 0;");
        }
        __syncthreads();

        if (act) {
            const float* bL = &sL[buf * (CC * W_)];
            const float* bR = &sR[buf * (CC * RW)];
            const int ab = xb - i0 + 24;   // window base in padded sR row
            #pragma unroll
            for (int cc = 0; cc < CC; cc++) {
                float4 Lq = *(const float4*)(bL + cc * W_ + xb);
                float  Ls = bL[cc * W_ + xb + 4];   // lane 59: harmless overread
                ull Le0 = pk(Lq.x, Lq.y);           // aligned: elided by ptxas
                ull Le1 = pk(Lq.z, Lq.w);
                ull Lo0 = pk(Lq.y, Lq.z);           // 2 MOVs
                ull Lo1 = pk(Lq.w, Ls);             // 2 MOVs

                // P[i] = (R[xb-i0-24+2i], R[xb-i0-24+2i+1]) — aligned quad halves
                ull P[14];
                #pragma unroll
                for (int m = 0; m < 7; m++) {
                    float4 qv = *(const float4*)(bR + cc * RW + ab + 4 * m);
                    P[2*m]   = pk(qv.x, qv.y);
                    P[2*m+1] = pk(qv.z, qv.w);
                }

                #pragma unroll
                for (int j = 0; j < 12; j++) {
                    fma2(accE[j][0], Le0, P[12 - j]);
                    fma2(accO[j][0], Lo0, P[12 - j]);
                    fma2(accE[j][1], Le1, P[13 - j]);
                    fma2(accO[j][1], Lo1, P[13 - j]);
                }
            }
        }
        __syncthreads();
    }

    const float s = 1.0f / 128.0f;
    if (act) {
        #pragma unroll
        for (int j = 0; j < 12; j++) {
            const int de = i0 + 2 * j;
            float a0, a1, a2, a3;
            upk(accE[j][0], a0, a1);
            upk(accE[j][1], a2, a3);
            float4 o;
            o.x = a0 * s; o.y = a1 * s; o.z = a2 * s; o.w = a3 * s;
            *(float4*)(out + (((size_t)b * V_ + de) * H_ + h) * W_ + xb) = o;

            float b0, b1, b2, b3;
            upk(accO[j][0], b0, b1);
            upk(accO[j][1], b2, b3);
            float* oo = out + (((size_t)b * V_ + de + 1) * H_ + h) * W_ + xb;
            oo[1] = b0 * s;
            oo[2] = b1 * s;
            oo[3] = b2 * s;
            if (xg < 59) oo[4] = b3 * s;     // x=xb+4; skip x=240 (lane 59)
        }
    } else if (xg == 60) {
        // out[x=0, odd d] is never produced by the odd pipeline; it's 0 (x<d).
        #pragma unroll
        for (int j = 0; j < 12; j++) {
            const int d = i0 + 2 * j + 1;
            out[(((size_t)b * V_ + d) * H_ + h) * W_] = 0.0f;
        }
    }
}

extern "C" void kernel_launch(void* const* d_in, const int* in_sizes, int n_in,
                              void* d_out, int out_size)
{
    const float* L = (const float*)d_in[0];
    const float* R = (const float*)d_in[1];
    float* out = (float*)d_out;

    const int smem_bytes = (2 * CC * W_ + 2 * CC * RW) * (int)sizeof(float); // 67584
    cudaFuncSetAttribute(cv_kernel, cudaFuncAttributeMaxDynamicSharedMemorySize,
                         smem_bytes);
    cv_kernel<<<dim3(H_, B_), THREADS, smem_bytes>>>(L, R, out);
}